// round 15
// baseline (speedup 1.0000x reference)
#include <cuda_runtime.h>

#define POOL 7
#define FW 128
#define FC 1024
#define CG (FC / 4)          // 256 float4 channel-groups per pixel
#define TPB 128              // 2 groups per thread per cell

__device__ __forceinline__ float4 bilin4(float4 tl, float4 tr, float4 bl, float4 br,
                                         float fx, float fy) {
    float4 o;
    float top, bot;
    top = tl.x + (tr.x - tl.x) * fx;
    bot = bl.x + (br.x - bl.x) * fx;
    o.x = top + (bot - top) * fy;
    top = tl.y + (tr.y - tl.y) * fx;
    bot = bl.y + (br.y - bl.y) * fx;
    o.y = top + (bot - top) * fy;
    top = tl.z + (tr.z - tl.z) * fx;
    bot = bl.z + (br.z - bl.z) * fx;
    o.z = top + (bot - top) * fy;
    top = tl.w + (tr.w - tl.w) * fx;
    bot = bl.w + (br.w - bl.w) * fx;
    o.w = top + (bot - top) * fy;
    return o;
}

__global__ __launch_bounds__(TPB)
void roi_pair_flat_kernel(const float* __restrict__ feat,
                          const float* __restrict__ rois,
                          float* __restrict__ out) {
    const int xg  = blockIdx.x;           // 0..3 -> px = 2*xg (and 2*xg+1 if xg<3)
    const int py  = blockIdx.y;           // 0..6
    const int roi = blockIdx.z;           // 0..511

    const float4 r = __ldg(((const float4*)rois) + roi);
    const int ymin = (int)r.x;
    const int xmin = (int)r.y;
    const int ymax = (int)r.z;
    const int xmax = (int)r.w;

    const int ylim = ymax - ymin;
    const int xlim = xmax - xmin;
    const float hs = (float)(ylim + 1) / (float)POOL;
    const float ws = (float)(xlim + 1) / (float)POOL;

    // shared row geometry
    const float sy = (float)py * hs;
    const int y0 = (int)floorf(sy);
    const int y1 = min(y0 + 1, ylim);
    const float fy = sy - (float)y0;
    const bool ny = (y1 != y0) && (fy != 0.0f);

    const float4* __restrict__ featv = (const float4*)feat;
    const int t = threadIdx.x;            // groups t and t+128
    const size_t row0 = ((size_t)(ymin + y0) * FW + xmin) * CG + t;
    const size_t row1 = ((size_t)(ymin + y1) * FW + xmin) * CG + t;

    // ---- cell A geometry ----
    const int pxa = 2 * xg;
    const float sxa = (float)pxa * ws;
    const int xa0 = (int)floorf(sxa);
    const int xa1 = min(xa0 + 1, xlim);
    const float fxa = sxa - (float)xa0;
    const bool nxa = (xa1 != xa0) && (fxa != 0.0f);

    // ---- cell B geometry (absent for xg==3) ----
    const bool hasb = (xg < 3);
    const int pxb = pxa + 1;
    const float sxb = (float)pxb * ws;
    const int xb0 = (int)floorf(sxb);
    const int xb1 = min(xb0 + 1, xlim);
    const float fxb = sxb - (float)xb0;
    const bool nxb = (xb1 != xb0) && (fxb != 0.0f);

    // ---- cell A loads (flat, warp-uniform predication; R5/R12 pattern) ----
    const float4 tla0 = featv[row0 + (size_t)xa0 * CG];
    const float4 tla1 = featv[row0 + (size_t)xa0 * CG + TPB];
    float4 tra0 = tla0, tra1 = tla1;
    if (nxa) {
        tra0 = featv[row0 + (size_t)xa1 * CG];
        tra1 = featv[row0 + (size_t)xa1 * CG + TPB];
    }
    float4 bla0 = tla0, bla1 = tla1;
    if (ny) {
        bla0 = featv[row1 + (size_t)xa0 * CG];
        bla1 = featv[row1 + (size_t)xa0 * CG + TPB];
    }
    float4 bra0, bra1;
    if (nxa && ny) {
        bra0 = featv[row1 + (size_t)xa1 * CG];
        bra1 = featv[row1 + (size_t)xa1 * CG + TPB];
    } else if (ny)  { bra0 = bla0; bra1 = bla1; }
    else if (nxa)   { bra0 = tra0; bra1 = tra1; }
    else            { bra0 = tla0; bra1 = tla1; }

    // ---- cell B loads (duplicates of A's addresses merge in L1/MSHR) ----
    float4 tlb0, tlb1, trb0, trb1, blb0, blb1, brb0, brb1;
    if (hasb) {
        tlb0 = featv[row0 + (size_t)xb0 * CG];
        tlb1 = featv[row0 + (size_t)xb0 * CG + TPB];
        trb0 = tlb0; trb1 = tlb1;
        if (nxb) {
            trb0 = featv[row0 + (size_t)xb1 * CG];
            trb1 = featv[row0 + (size_t)xb1 * CG + TPB];
        }
        blb0 = tlb0; blb1 = tlb1;
        if (ny) {
            blb0 = featv[row1 + (size_t)xb0 * CG];
            blb1 = featv[row1 + (size_t)xb0 * CG + TPB];
        }
        if (nxb && ny) {
            brb0 = featv[row1 + (size_t)xb1 * CG];
            brb1 = featv[row1 + (size_t)xb1 * CG + TPB];
        } else if (ny)  { brb0 = blb0; brb1 = blb1; }
        else if (nxb)   { brb0 = trb0; brb1 = trb1; }
        else            { brb0 = tlb0; brb1 = tlb1; }
    }

    // ---- compute + streaming stores ----
    const size_t outbase = ((size_t)roi * (POOL * POOL) + (size_t)py * POOL) * CG + t;
    float4* __restrict__ outv = (float4*)out;

    const float4 oa0 = bilin4(tla0, tra0, bla0, bra0, fxa, fy);
    const float4 oa1 = bilin4(tla1, tra1, bla1, bra1, fxa, fy);
    __stcs(outv + outbase + (size_t)pxa * CG,       oa0);
    __stcs(outv + outbase + (size_t)pxa * CG + TPB, oa1);

    if (hasb) {
        const float4 ob0 = bilin4(tlb0, trb0, blb0, brb0, fxb, fy);
        const float4 ob1 = bilin4(tlb1, trb1, blb1, brb1, fxb, fy);
        __stcs(outv + outbase + (size_t)pxb * CG,       ob0);
        __stcs(outv + outbase + (size_t)pxb * CG + TPB, ob1);
    }
}

extern "C" void kernel_launch(void* const* d_in, const int* in_sizes, int n_in,
                              void* d_out, int out_size) {
    const float* feat = (const float*)d_in[0];   // (1,128,128,1024) fp32
    const float* rois = (const float*)d_in[1];   // (512,4) fp32
    float* out = (float*)d_out;                  // (512, 7*7*1024) fp32

    dim3 grid(4, POOL, 512);
    roi_pair_flat_kernel<<<grid, TPB>>>(feat, rois, out);
}

// round 16
// speedup vs baseline: 1.2484x; 1.2484x over previous
#include <cuda_runtime.h>

#define POOL 7
#define FW 128
#define FC 1024
#define CG (FC / 4)          // 256 float4 channel-groups per pixel
#define TPB 64               // each thread handles 4 channel groups

__device__ __forceinline__ float4 bilin4(float4 tl, float4 tr, float4 bl, float4 br,
                                         float fx, float fy) {
    float4 o;
    float top, bot;
    top = tl.x + (tr.x - tl.x) * fx;
    bot = bl.x + (br.x - bl.x) * fx;
    o.x = top + (bot - top) * fy;
    top = tl.y + (tr.y - tl.y) * fx;
    bot = bl.y + (br.y - bl.y) * fx;
    o.y = top + (bot - top) * fy;
    top = tl.z + (tr.z - tl.z) * fx;
    bot = bl.z + (br.z - bl.z) * fx;
    o.z = top + (bot - top) * fy;
    top = tl.w + (tr.w - tl.w) * fx;
    bot = bl.w + (br.w - bl.w) * fx;
    o.w = top + (bot - top) * fy;
    return o;
}

__global__ __launch_bounds__(TPB)
void roi_bilinear_kernel(const float* __restrict__ feat,
                         const float* __restrict__ rois,
                         float* __restrict__ out) {
    const int px  = blockIdx.x;           // 0..6
    const int py  = blockIdx.y;           // 0..6
    const int roi = blockIdx.z;           // 0..511

    const float4 r = __ldg(((const float4*)rois) + roi);
    const int ymin = (int)r.x;
    const int xmin = (int)r.y;
    const int ymax = (int)r.z;
    const int xmax = (int)r.w;

    const float h = (float)(ymax - ymin + 1);
    const float w = (float)(xmax - xmin + 1);

    const float sy = (float)py * (h / (float)POOL);
    const float sx = (float)px * (w / (float)POOL);

    const int y0 = (int)floorf(sy);
    const int x0 = (int)floorf(sx);
    const int y1 = min(y0 + 1, ymax - ymin);
    const int x1 = min(x0 + 1, xmax - xmin);

    const float fy = sy - (float)y0;
    const float fx = sx - (float)x0;

    const bool needx = (x1 != x0) && (fx != 0.0f);
    const bool needy = (y1 != y0) && (fy != 0.0f);

    // 32-bit offsets (float4 units; max 128*128*256 = 4.19M)
    const unsigned b00 = (unsigned)((ymin + y0) * FW + (xmin + x0)) * CG;
    const unsigned b01 = (unsigned)((ymin + y0) * FW + (xmin + x1)) * CG;
    const unsigned b10 = (unsigned)((ymin + y1) * FW + (xmin + x0)) * CG;
    const unsigned b11 = (unsigned)((ymin + y1) * FW + (xmin + x1)) * CG;

    // Predicated ADDRESSES instead of predicated loads: dead corners are
    // redirected to an already-loaded line (same-line L1 hit, zero extra LTS
    // bytes) so the load batch is branch-free straight-line SASS.
    const unsigned o01 = needx ? b01 : b00;
    const unsigned o10 = needy ? b10 : b00;
    const unsigned o11 = needy ? (needx ? b11 : b10) : o01;

    const float4* __restrict__ featv = (const float4*)feat;
    const unsigned t = threadIdx.x;       // groups t, t+64, t+128, t+192

    // 16 unconditional independent 128-bit loads — no BSSY/BSYNC anywhere
    float4 tl[4], tr[4], bl[4], br[4];
    #pragma unroll
    for (int k = 0; k < 4; ++k) tl[k] = __ldg(featv + b00 + t + k * TPB);
    #pragma unroll
    for (int k = 0; k < 4; ++k) tr[k] = __ldg(featv + o01 + t + k * TPB);
    #pragma unroll
    for (int k = 0; k < 4; ++k) bl[k] = __ldg(featv + o10 + t + k * TPB);
    #pragma unroll
    for (int k = 0; k < 4; ++k) br[k] = __ldg(featv + o11 + t + k * TPB);

    const int cell = py * POOL + px;
    float4* __restrict__ outv =
        (float4*)(out + ((size_t)roi * (POOL * POOL) + cell) * FC);

    #pragma unroll
    for (int k = 0; k < 4; ++k) {
        const float4 o = bilin4(tl[k], tr[k], bl[k], br[k], fx, fy);
        __stcs(outv + t + k * TPB, o);
    }
}

extern "C" void kernel_launch(void* const* d_in, const int* in_sizes, int n_in,
                              void* d_out, int out_size) {
    const float* feat = (const float*)d_in[0];   // (1,128,128,1024) fp32
    const float* rois = (const float*)d_in[1];   // (512,4) fp32
    float* out = (float*)d_out;                  // (512, 7*7*1024) fp32

    dim3 grid(POOL, POOL, 512);
    roi_bilinear_kernel<<<grid, TPB>>>(feat, rois, out);
}